// round 1
// baseline (speedup 1.0000x reference)
#include <cuda_runtime.h>
#include <math.h>

#define B_  8
#define L_  1024
#define S_  512
#define SD_ 512
#define VD_ 64
#define DM_ 512
#define D3_ 192
#define NH_ 8
#define DK_ 64

// ---------------- scratch (device globals; no allocation) ----------------
__device__ float g_mean_rel[S_ * D3_];
__device__ float g_ms   [B_ * S_ * D3_];
__device__ float g_xpe  [B_ * S_ * D3_];
__device__ float g_gamma[B_ * S_ * DM_];
__device__ float g_q    [B_ * L_ * DM_];
__device__ float g_k    [B_ * S_ * DM_];
__device__ float g_v    [B_ * S_ * DM_];
__device__ float g_att  [B_ * L_ * DM_];
__device__ float g_fc   [B_ * L_ * DM_];

// ---------------- K1: mean_rel[j,d] = mean_i rel_table[clip(j-i)+30, d] ----
__global__ void mean_rel_kernel(const float* __restrict__ rel) {
    __shared__ float srel[61 * D3_];
    for (int i = threadIdx.x; i < 61 * D3_; i += blockDim.x) srel[i] = rel[i];
    __syncthreads();
    int j = blockIdx.x, d = threadIdx.x;
    float sum = 0.f;
    for (int i = 0; i < S_; i++) {
        int r = j - i;
        r = min(30, max(-30, r)) + 30;
        sum += srel[r * D3_ + d];
    }
    g_mean_rel[j * D3_ + d] = sum * (1.f / S_);
}

// ---------------- K2: ms = concat(conv3, conv5, conv7)(x_velocity) --------
template <int KW>
__device__ __forceinline__ void conv_body(const float (*sx)[VD_],
                                          const float* __restrict__ w,
                                          float bias, float* acc) {
#pragma unroll
    for (int s = 0; s < 32; s++) acc[s] = bias;
    const int off0 = 3 - KW / 2;
    for (int cin = 0; cin < VD_; cin++) {
#pragma unroll
        for (int t = 0; t < KW; t++) {
            float wv = __ldg(w + cin * KW + t);
#pragma unroll
            for (int s = 0; s < 32; s++)
                acc[s] = fmaf(wv, sx[s + off0 + t][cin], acc[s]);
        }
    }
}

__global__ void conv_kernel(const float* __restrict__ xv,
                            const float* __restrict__ w3, const float* __restrict__ b3,
                            const float* __restrict__ w5, const float* __restrict__ b5,
                            const float* __restrict__ w7, const float* __restrict__ b7) {
    int b = blockIdx.x, s0 = blockIdx.y * 32;
    __shared__ float sx[38][VD_];
    for (int idx = threadIdx.x; idx < 38 * VD_; idx += 192) {
        int r = idx >> 6, cin = idx & 63;
        int s = s0 + r - 3;
        sx[r][cin] = ((unsigned)s < S_) ? xv[(b * S_ + s) * VD_ + cin] : 0.f;
    }
    __syncthreads();
    int c = threadIdx.x;
    float acc[32];
    if (c < 64)       conv_body<3>(sx, w3 + c * 64 * 3,        b3[c],       acc);
    else if (c < 128) conv_body<5>(sx, w5 + (c - 64) * 64 * 5, b5[c - 64],  acc);
    else              conv_body<7>(sx, w7 + (c - 128) * 64 * 7, b7[c - 128], acc);
#pragma unroll
    for (int s = 0; s < 32; s++)
        g_ms[((b * S_) + s0 + s) * D3_ + c] = acc[s];
}

// ---------------- K3: x_pe ------------------------------------------------
__global__ void xpe_kernel(const float* __restrict__ rel,
                           const float* __restrict__ dww,
                           const float* __restrict__ dwb) {
    int bs = blockIdx.x;
    int s = bs & (S_ - 1);
    int d = threadIdx.x;
    int base = bs * D3_ + d;
    float msv = g_ms[base];
    float center = msv + rel[30 * D3_ + d];
    float left  = (s > 0)      ? g_ms[base - D3_] + rel[29 * D3_ + d] : 0.f;
    float right = (s < S_ - 1) ? g_ms[base + D3_] + rel[31 * D3_ + d] : 0.f;
    float diag = dww[d * 3 + 0] * left + dww[d * 3 + 1] * center +
                 dww[d * 3 + 2] * right + dwb[d];
    g_xpe[base] = msv + g_mean_rel[s * D3_ + d] + (diag - center) * (1.f / S_);
}

// ---------------- generic fp32 GEMM: C[m,n] = sum_k A[m,k]*W[n,k] ---------
// BM=BN=128, BK=8, 256 threads, 8x8 per thread.  ACT: 0=none, 1=sigmoid.
template <int ACT>
__global__ void __launch_bounds__(256) gemm_k(const float* __restrict__ A,
                                              const float* __restrict__ W,
                                              const float* __restrict__ bias,
                                              float* __restrict__ C,
                                              int M, int N, int K) {
    __shared__ float As[8][132];
    __shared__ float Ws[8][132];
    int tid = threadIdx.x;
    int m0 = blockIdx.y * 128, n0 = blockIdx.x * 128;
    int lr = tid >> 1, lc = (tid & 1) * 4;
    const float* Ap = A + (size_t)(m0 + lr) * K + lc;
    const float* Wp = W + (size_t)(n0 + lr) * K + lc;
    int ty = tid >> 4, tx = tid & 15;
    float acc[8][8];
#pragma unroll
    for (int i = 0; i < 8; i++)
#pragma unroll
        for (int j = 0; j < 8; j++) acc[i][j] = 0.f;

    for (int k0 = 0; k0 < K; k0 += 8) {
        float4 av = *(const float4*)(Ap + k0);
        float4 wv = *(const float4*)(Wp + k0);
        As[lc + 0][lr] = av.x; As[lc + 1][lr] = av.y;
        As[lc + 2][lr] = av.z; As[lc + 3][lr] = av.w;
        Ws[lc + 0][lr] = wv.x; Ws[lc + 1][lr] = wv.y;
        Ws[lc + 2][lr] = wv.z; Ws[lc + 3][lr] = wv.w;
        __syncthreads();
#pragma unroll
        for (int k = 0; k < 8; k++) {
            float4 a0 = *(float4*)&As[k][ty * 8];
            float4 a1 = *(float4*)&As[k][ty * 8 + 4];
            float4 b0 = *(float4*)&Ws[k][tx * 8];
            float4 b1 = *(float4*)&Ws[k][tx * 8 + 4];
            float aa[8] = {a0.x, a0.y, a0.z, a0.w, a1.x, a1.y, a1.z, a1.w};
            float bb[8] = {b0.x, b0.y, b0.z, b0.w, b1.x, b1.y, b1.z, b1.w};
#pragma unroll
            for (int i = 0; i < 8; i++)
#pragma unroll
                for (int j = 0; j < 8; j++)
                    acc[i][j] = fmaf(aa[i], bb[j], acc[i][j]);
        }
        __syncthreads();
    }
#pragma unroll
    for (int i = 0; i < 8; i++) {
        int m = m0 + ty * 8 + i;
#pragma unroll
        for (int j = 0; j < 8; j++) {
            int n = n0 + tx * 8 + j;
            float v = acc[i][j];
            if (bias) v += bias[n];
            if (ACT == 1) v = 1.f / (1.f + expf(-v));
            C[(size_t)m * N + n] = v;
        }
    }
}

// ---------------- attention: per (b,h,64-row L tile), full S=512 ----------
// smem: Ps[64][513], Qt[64][68] (d-major), Kt[64][68] (d-major / reused as V [s][68])
#define ATT_SMEM ((64 * 513 + 2 * 64 * 68) * 4)

__global__ void __launch_bounds__(256) attn_kernel() {
    extern __shared__ float sm[];
    float* Ps = sm;                 // 64 x 513
    float* Qt = sm + 64 * 513;      // 64 x 68
    float* Kt = Qt + 64 * 68;       // 64 x 68
    int l0 = blockIdx.x * 64;
    int h = blockIdx.y, b = blockIdx.z;
    int tid = threadIdx.x;
    int ty = tid >> 4, tx = tid & 15;

    // load Q tile transposed (d-major)
    for (int idx = tid; idx < 64 * 64; idx += 256) {
        int l = idx >> 6, d = idx & 63;
        Qt[d * 68 + l] = g_q[(size_t)(b * L_ + l0 + l) * DM_ + h * DK_ + d];
    }

    // ---- scores ----
    for (int sc = 0; sc < 8; sc++) {
        __syncthreads();
        for (int idx = tid; idx < 64 * 64; idx += 256) {
            int s = idx >> 6, d = idx & 63;
            Kt[d * 68 + s] = g_k[(size_t)(b * S_ + sc * 64 + s) * DM_ + h * DK_ + d];
        }
        __syncthreads();
        float acc[4][4];
#pragma unroll
        for (int i = 0; i < 4; i++)
#pragma unroll
            for (int j = 0; j < 4; j++) acc[i][j] = 0.f;
        for (int d = 0; d < 64; d++) {
            float4 a = *(float4*)&Qt[d * 68 + ty * 4];
            float4 kv = *(float4*)&Kt[d * 68 + tx * 4];
            float aa[4] = {a.x, a.y, a.z, a.w};
            float bb[4] = {kv.x, kv.y, kv.z, kv.w};
#pragma unroll
            for (int i = 0; i < 4; i++)
#pragma unroll
                for (int j = 0; j < 4; j++)
                    acc[i][j] = fmaf(aa[i], bb[j], acc[i][j]);
        }
#pragma unroll
        for (int i = 0; i < 4; i++)
#pragma unroll
            for (int j = 0; j < 4; j++)
                Ps[(ty * 4 + i) * 513 + sc * 64 + tx * 4 + j] = acc[i][j] * 0.125f;
    }
    __syncthreads();

    // ---- softmax over full row (4 threads per row) ----
    {
        int r = tid >> 2, q = tid & 3;
        float* row = Ps + r * 513 + q * 128;
        float mx = -1e30f;
        for (int j = 0; j < 128; j++) mx = fmaxf(mx, row[j]);
        mx = fmaxf(mx, __shfl_xor_sync(0xffffffffu, mx, 1));
        mx = fmaxf(mx, __shfl_xor_sync(0xffffffffu, mx, 2));
        float sum = 0.f;
        for (int j = 0; j < 128; j++) {
            float e = expf(row[j] - mx);
            row[j] = e;
            sum += e;
        }
        sum += __shfl_xor_sync(0xffffffffu, sum, 1);
        sum += __shfl_xor_sync(0xffffffffu, sum, 2);
        float inv = 1.f / sum;
        for (int j = 0; j < 128; j++) row[j] *= inv;
    }

    // ---- P @ V ----
    float oacc[4][4];
#pragma unroll
    for (int i = 0; i < 4; i++)
#pragma unroll
        for (int j = 0; j < 4; j++) oacc[i][j] = 0.f;
    for (int sc = 0; sc < 8; sc++) {
        __syncthreads();
        for (int idx = tid; idx < 64 * 64; idx += 256) {
            int s = idx >> 6, d = idx & 63;
            Kt[s * 68 + d] = g_v[(size_t)(b * S_ + sc * 64 + s) * DM_ + h * DK_ + d];
        }
        __syncthreads();
        for (int s = 0; s < 64; s++) {
            float4 vv = *(float4*)&Kt[s * 68 + tx * 4];
            float bb[4] = {vv.x, vv.y, vv.z, vv.w};
#pragma unroll
            for (int i = 0; i < 4; i++) {
                float p = Ps[(ty * 4 + i) * 513 + sc * 64 + s];
#pragma unroll
                for (int j = 0; j < 4; j++)
                    oacc[i][j] = fmaf(p, bb[j], oacc[i][j]);
            }
        }
    }
#pragma unroll
    for (int i = 0; i < 4; i++)
#pragma unroll
        for (int j = 0; j < 4; j++)
            g_att[(size_t)(b * L_ + l0 + ty * 4 + i) * DM_ + h * DK_ + tx * 4 + j] = oacc[i][j];
}

// ---------------- final: gate * fc + residual + LayerNorm -----------------
__global__ void final_kernel(const float* __restrict__ xs,
                             const float* __restrict__ lng,
                             const float* __restrict__ lnb,
                             float* __restrict__ out) {
    int row = blockIdx.x;
    int b = row >> 10;
    int l = row & 1023;
    int s = l & (S_ - 1);
    int d1 = threadIdx.x, d2 = threadIdx.x + 256;
    size_t ro = (size_t)row * DM_;
    size_t go = (size_t)(b * S_ + s) * DM_;
    float v1 = xs[ro + d1] + g_gamma[go + d1] * g_fc[ro + d1];
    float v2 = xs[ro + d2] + g_gamma[go + d2] * g_fc[ro + d2];
    float sum = v1 + v2, sq = v1 * v1 + v2 * v2;
#pragma unroll
    for (int o = 16; o; o >>= 1) {
        sum += __shfl_xor_sync(0xffffffffu, sum, o);
        sq  += __shfl_xor_sync(0xffffffffu, sq,  o);
    }
    __shared__ float rs[8], rq[8];
    int w = threadIdx.x >> 5, lane = threadIdx.x & 31;
    if (lane == 0) { rs[w] = sum; rq[w] = sq; }
    __syncthreads();
    float tsum = 0.f, tsq = 0.f;
#pragma unroll
    for (int i = 0; i < 8; i++) { tsum += rs[i]; tsq += rq[i]; }
    float mu = tsum * (1.f / DM_);
    float var = tsq * (1.f / DM_) - mu * mu;
    float inv = rsqrtf(var + 1e-5f);
    out[ro + d1] = (v1 - mu) * inv * lng[d1] + lnb[d1];
    out[ro + d2] = (v2 - mu) * inv * lng[d2] + lnb[d2];
}

// ---------------- launch ---------------------------------------------------
extern "C" void kernel_launch(void* const* d_in, const int* in_sizes, int n_in,
                              void* d_out, int out_size) {
    const float* x_spatial  = (const float*)d_in[0];
    const float* x_velocity = (const float*)d_in[1];
    const float* w_gamma    = (const float*)d_in[2];
    const float* w3 = (const float*)d_in[3];  const float* b3 = (const float*)d_in[4];
    const float* w5 = (const float*)d_in[5];  const float* b5 = (const float*)d_in[6];
    const float* w7 = (const float*)d_in[7];  const float* b7 = (const float*)d_in[8];
    const float* rel = (const float*)d_in[9];
    const float* dww = (const float*)d_in[10]; const float* dwb = (const float*)d_in[11];
    const float* wq  = (const float*)d_in[12];
    const float* wk  = (const float*)d_in[13];
    const float* wv  = (const float*)d_in[14];
    const float* fcw = (const float*)d_in[15]; const float* fcb = (const float*)d_in[16];
    const float* lng = (const float*)d_in[17]; const float* lnb = (const float*)d_in[18];
    float* out = (float*)d_out;

    float *p_gamma, *p_q, *p_k, *p_v, *p_att, *p_fc, *p_xpe;
    cudaGetSymbolAddress((void**)&p_gamma, g_gamma);
    cudaGetSymbolAddress((void**)&p_q,     g_q);
    cudaGetSymbolAddress((void**)&p_k,     g_k);
    cudaGetSymbolAddress((void**)&p_v,     g_v);
    cudaGetSymbolAddress((void**)&p_att,   g_att);
    cudaGetSymbolAddress((void**)&p_fc,    g_fc);
    cudaGetSymbolAddress((void**)&p_xpe,   g_xpe);

    cudaFuncSetAttribute(attn_kernel,
                         cudaFuncAttributeMaxDynamicSharedMemorySize, ATT_SMEM);

    // 1. B-independent mean_rel table
    mean_rel_kernel<<<S_, D3_>>>(rel);
    // 2. multi-scale convs
    conv_kernel<<<dim3(B_, S_ / 32), D3_>>>(x_velocity, w3, b3, w5, b5, w7, b7);
    // 3. rel-pos encoding (elementwise)
    xpe_kernel<<<B_ * S_, D3_>>>(rel, dww, dwb);
    // 4. gamma = sigmoid(xv @ w_gamma^T)      [4096 x 64 x 512]
    gemm_k<1><<<dim3(DM_ / 128, (B_ * S_) / 128), 256>>>(x_velocity, w_gamma, nullptr,
                                                         p_gamma, B_ * S_, DM_, VD_);
    // 5. q = x_spatial @ wq^T                 [8192 x 512 x 512]
    gemm_k<0><<<dim3(DM_ / 128, (B_ * L_) / 128), 256>>>(x_spatial, wq, nullptr,
                                                         p_q, B_ * L_, DM_, SD_);
    // 6/7. k,v = x_pe @ wk^T / wv^T           [4096 x 192 x 512]
    gemm_k<0><<<dim3(DM_ / 128, (B_ * S_) / 128), 256>>>(p_xpe, wk, nullptr,
                                                         p_k, B_ * S_, DM_, D3_);
    gemm_k<0><<<dim3(DM_ / 128, (B_ * S_) / 128), 256>>>(p_xpe, wv, nullptr,
                                                         p_v, B_ * S_, DM_, D3_);
    // 8. attention
    attn_kernel<<<dim3(L_ / 64, NH_, B_), 256, ATT_SMEM>>>();
    // 9. fc = att @ fc_w^T + fc_b             [8192 x 512 x 512]
    gemm_k<0><<<dim3(DM_ / 128, (B_ * L_) / 128), 256>>>(p_att, fcw, fcb,
                                                         p_fc, B_ * L_, DM_, DM_);
    // 10. gate + residual + layernorm
    final_kernel<<<B_ * L_, 256>>>(x_spatial, lng, lnb, out);
}

// round 4
// speedup vs baseline: 2.7996x; 2.7996x over previous
#include <cuda_runtime.h>
#include <math.h>
#include <stdint.h>

#define B_  8
#define L_  1024
#define S_  512
#define SD_ 512
#define VD_ 64
#define DM_ 512
#define D3_ 192
#define NH_ 8
#define DK_ 64
#define BH_ (B_ * NH_)

// ---------------- scratch (device globals; no allocation) ----------------
__device__ float g_mean_rel[S_ * D3_];
__device__ float g_ms    [B_ * S_ * D3_];
__device__ float g_xpe   [B_ * S_ * D3_];
__device__ float g_gamma [B_ * S_ * DM_];
__device__ float g_q     [B_ * L_ * DM_];
__device__ float g_k     [B_ * S_ * DM_];
__device__ float g_v     [B_ * S_ * DM_];
__device__ float g_vt    [BH_ * DK_ * S_];
__device__ float g_scores[BH_ * L_ * S_];    // 128 MB, reused in-place for probs
__device__ float g_att   [B_ * L_ * DM_];
__device__ float g_fc    [B_ * L_ * DM_];

// ---------------- tf32 helpers ----------------
__device__ __forceinline__ uint32_t f2tf(float x) {
    uint32_t r;
    asm("cvt.rna.tf32.f32 %0, %1;" : "=r"(r) : "f"(x));
    return r;
}
__device__ __forceinline__ void mma_tf32(float* c, const uint32_t* a, const uint32_t* b) {
    asm volatile(
        "mma.sync.aligned.m16n8k8.row.col.f32.tf32.tf32.f32 "
        "{%0,%1,%2,%3}, {%4,%5,%6,%7}, {%8,%9}, {%0,%1,%2,%3};\n"
        : "+f"(c[0]), "+f"(c[1]), "+f"(c[2]), "+f"(c[3])
        : "r"(a[0]), "r"(a[1]), "r"(a[2]), "r"(a[3]), "r"(b[0]), "r"(b[1]));
}

// ================= K1: mean_rel =================
__global__ void mean_rel_kernel(const float* __restrict__ rel) {
    __shared__ float srel[61 * D3_];
    for (int i = threadIdx.x; i < 61 * D3_; i += blockDim.x) srel[i] = rel[i];
    __syncthreads();
    int j = blockIdx.x, d = threadIdx.x;
    float sum = 0.f;
    for (int i = 0; i < S_; i++) {
        int r = j - i;
        r = min(30, max(-30, r)) + 30;
        sum += srel[r * D3_ + d];
    }
    g_mean_rel[j * D3_ + d] = sum * (1.f / S_);
}

// ================= K2: multi-scale convs =================
template <int KW>
__device__ __forceinline__ void conv_body(const float (*sx)[VD_],
                                          const float* __restrict__ w,
                                          float bias, float* acc) {
#pragma unroll
    for (int s = 0; s < 32; s++) acc[s] = bias;
    const int off0 = 3 - KW / 2;
    for (int cin = 0; cin < VD_; cin++) {
#pragma unroll
        for (int t = 0; t < KW; t++) {
            float wv = __ldg(w + cin * KW + t);
#pragma unroll
            for (int s = 0; s < 32; s++)
                acc[s] = fmaf(wv, sx[s + off0 + t][cin], acc[s]);
        }
    }
}

__global__ void conv_kernel(const float* __restrict__ xv,
                            const float* __restrict__ w3, const float* __restrict__ b3,
                            const float* __restrict__ w5, const float* __restrict__ b5,
                            const float* __restrict__ w7, const float* __restrict__ b7) {
    int b = blockIdx.x, s0 = blockIdx.y * 32;
    __shared__ float sx[38][VD_];
    for (int idx = threadIdx.x; idx < 38 * VD_; idx += 192) {
        int r = idx >> 6, cin = idx & 63;
        int s = s0 + r - 3;
        sx[r][cin] = ((unsigned)s < S_) ? xv[(b * S_ + s) * VD_ + cin] : 0.f;
    }
    __syncthreads();
    int c = threadIdx.x;
    float acc[32];
    if (c < 64)       conv_body<3>(sx, w3 + c * 64 * 3,         b3[c],        acc);
    else if (c < 128) conv_body<5>(sx, w5 + (c - 64) * 64 * 5,  b5[c - 64],   acc);
    else              conv_body<7>(sx, w7 + (c - 128) * 64 * 7, b7[c - 128],  acc);
#pragma unroll
    for (int s = 0; s < 32; s++)
        g_ms[((b * S_) + s0 + s) * D3_ + c] = acc[s];
}

// ================= K3: x_pe =================
__global__ void xpe_kernel(const float* __restrict__ rel,
                           const float* __restrict__ dww,
                           const float* __restrict__ dwb) {
    int bs = blockIdx.x;
    int s = bs & (S_ - 1);
    int d = threadIdx.x;
    int base = bs * D3_ + d;
    float msv = g_ms[base];
    float center = msv + rel[30 * D3_ + d];
    float left  = (s > 0)      ? g_ms[base - D3_] + rel[29 * D3_ + d] : 0.f;
    float right = (s < S_ - 1) ? g_ms[base + D3_] + rel[31 * D3_ + d] : 0.f;
    float diag = dww[d * 3 + 0] * left + dww[d * 3 + 1] * center +
                 dww[d * 3 + 2] * right + dwb[d];
    g_xpe[base] = msv + g_mean_rel[s * D3_ + d] + (diag - center) * (1.f / S_);
}

// ================= tf32 mma.sync batched GEMM =================
// C[m,n] = sum_k A[m,k] * B[n,k]   (both K-major)
// CTA 128 x NT, 256 threads (8 warps), K-chunks of 32 floats, SW pipeline.
// EPI: 0 none, 1 sigmoid, 2 +bias
template <int NT, int EPI>
__global__ void __launch_bounds__(256) mma_gemm(
    const float* __restrict__ A, const float* __restrict__ Bw,
    const float* __restrict__ bias, float* __restrict__ C,
    int K, int lda, int ldb, int ldc,
    long long sAb, long long sAh, long long sBb, long long sBh,
    long long sCb, long long sCh)
{
    constexpr int WROWS = (NT == 128) ? 2 : 4;     // warps along M
    constexpr int WM  = 128 / WROWS;               // 64 or 32
    constexpr int WN  = NT / (8 / WROWS);          // 32
    constexpr int MT  = WM / 16;                   // m16 tiles per warp
    constexpr int NTT = WN / 8;                    // n8 tiles per warp
    constexpr int AIT = 4;                         // A float4 loads / thread
    constexpr int BIT = NT / 32;                   // B float4 loads / thread

    __shared__ uint32_t As[128][36];
    __shared__ uint32_t Bs[NT][36];

    int tid = threadIdx.x;
    int wid = tid >> 5, lane = tid & 31;
    int wm = (wid % WROWS) * WM;
    int wn = (wid / WROWS) * WN;
    int lg = lane >> 2, lr = lane & 3;

    int zb = blockIdx.z >> 3, zh = blockIdx.z & 7;
    const float* Ap = A + (size_t)zb * sAb + (size_t)zh * sAh +
                      (size_t)blockIdx.y * 128 * lda;
    const float* Bp = Bw + (size_t)zb * sBb + (size_t)zh * sBh +
                      (size_t)blockIdx.x * NT * ldb;
    float* Cp = C + (size_t)zb * sCb + (size_t)zh * sCh +
                (size_t)blockIdx.y * 128 * ldc + blockIdx.x * NT;

    float acc[MT][NTT][4];
#pragma unroll
    for (int i = 0; i < MT; i++)
#pragma unroll
        for (int j = 0; j < NTT; j++)
#pragma unroll
            for (int q = 0; q < 4; q++) acc[i][j][q] = 0.f;

    float4 pa[AIT], pb[BIT];
    int nch = K >> 5;

    // prefetch chunk 0
#pragma unroll
    for (int i = 0; i < AIT; i++) {
        int idx = i * 256 + tid, r = idx >> 3, c4 = idx & 7;
        pa[i] = *(const float4*)(Ap + (size_t)r * lda + c4 * 4);
    }
#pragma unroll
    for (int i = 0; i < BIT; i++) {
        int idx = i * 256 + tid, r = idx >> 3, c4 = idx & 7;
        pb[i] = *(const float4*)(Bp + (size_t)r * ldb + c4 * 4);
    }

    for (int c = 0; c < nch; c++) {
        // store current chunk to smem (cvt to tf32 once here)
#pragma unroll
        for (int i = 0; i < AIT; i++) {
            int idx = i * 256 + tid, r = idx >> 3, c4 = idx & 7;
            uint4 u = {f2tf(pa[i].x), f2tf(pa[i].y), f2tf(pa[i].z), f2tf(pa[i].w)};
            *(uint4*)&As[r][c4 * 4] = u;
        }
#pragma unroll
        for (int i = 0; i < BIT; i++) {
            int idx = i * 256 + tid, r = idx >> 3, c4 = idx & 7;
            uint4 u = {f2tf(pb[i].x), f2tf(pb[i].y), f2tf(pb[i].z), f2tf(pb[i].w)};
            *(uint4*)&Bs[r][c4 * 4] = u;
        }
        __syncthreads();
        // prefetch next chunk
        if (c + 1 < nch) {
            int kc = (c + 1) * 32;
#pragma unroll
            for (int i = 0; i < AIT; i++) {
                int idx = i * 256 + tid, r = idx >> 3, c4 = idx & 7;
                pa[i] = *(const float4*)(Ap + (size_t)r * lda + kc + c4 * 4);
            }
#pragma unroll
            for (int i = 0; i < BIT; i++) {
                int idx = i * 256 + tid, r = idx >> 3, c4 = idx & 7;
                pb[i] = *(const float4*)(Bp + (size_t)r * ldb + kc + c4 * 4);
            }
        }
        // compute 4 k-steps of 8
#pragma unroll
        for (int kk = 0; kk < 32; kk += 8) {
            uint32_t af[MT][4], bf[NTT][2];
#pragma unroll
            for (int mt = 0; mt < MT; mt++) {
                int r = wm + mt * 16 + lg;
                af[mt][0] = As[r][kk + lr];
                af[mt][1] = As[r + 8][kk + lr];
                af[mt][2] = As[r][kk + lr + 4];
                af[mt][3] = As[r + 8][kk + lr + 4];
            }
#pragma unroll
            for (int nt = 0; nt < NTT; nt++) {
                int r = wn + nt * 8 + lg;
                bf[nt][0] = Bs[r][kk + lr];
                bf[nt][1] = Bs[r][kk + lr + 4];
            }
#pragma unroll
            for (int mt = 0; mt < MT; mt++)
#pragma unroll
                for (int nt = 0; nt < NTT; nt++)
                    mma_tf32(acc[mt][nt], af[mt], bf[nt]);
        }
        __syncthreads();
    }

    // epilogue: C fragment -> gmem (float2 stores)
    int n0 = blockIdx.x * NT;
#pragma unroll
    for (int mt = 0; mt < MT; mt++) {
#pragma unroll
        for (int nt = 0; nt < NTT; nt++) {
            int r = wm + mt * 16 + lg;
            int cc = wn + nt * 8 + lr * 2;
            float v0 = acc[mt][nt][0], v1 = acc[mt][nt][1];
            float v2 = acc[mt][nt][2], v3 = acc[mt][nt][3];
            if (EPI == 1) {
                v0 = 1.f / (1.f + __expf(-v0));
                v1 = 1.f / (1.f + __expf(-v1));
                v2 = 1.f / (1.f + __expf(-v2));
                v3 = 1.f / (1.f + __expf(-v3));
            }
            if (EPI == 2) {
                float b0 = bias[n0 + cc], b1 = bias[n0 + cc + 1];
                v0 += b0; v1 += b1; v2 += b0; v3 += b1;
            }
            *(float2*)(Cp + (size_t)r * ldc + cc) = make_float2(v0, v1);
            *(float2*)(Cp + (size_t)(r + 8) * ldc + cc) = make_float2(v2, v3);
        }
    }
}

// ================= softmax over S=512 (scale 1/8 folded in) =================
__global__ void __launch_bounds__(256) softmax_kernel() {
    int row = blockIdx.x * 8 + (threadIdx.x >> 5);
    int lane = threadIdx.x & 31;
    float* p = g_scores + (size_t)row * S_;
    float4 v[4];
#pragma unroll
    for (int i = 0; i < 4; i++)
        v[i] = *(float4*)(p + i * 128 + lane * 4);
    float mx = -1e30f;
#pragma unroll
    for (int i = 0; i < 4; i++)
        mx = fmaxf(mx, fmaxf(fmaxf(v[i].x, v[i].y), fmaxf(v[i].z, v[i].w)));
#pragma unroll
    for (int o = 16; o; o >>= 1) mx = fmaxf(mx, __shfl_xor_sync(~0u, mx, o));
    float sum = 0.f;
#pragma unroll
    for (int i = 0; i < 4; i++) {
        v[i].x = __expf((v[i].x - mx) * 0.125f);
        v[i].y = __expf((v[i].y - mx) * 0.125f);
        v[i].z = __expf((v[i].z - mx) * 0.125f);
        v[i].w = __expf((v[i].w - mx) * 0.125f);
        sum += v[i].x + v[i].y + v[i].z + v[i].w;
    }
#pragma unroll
    for (int o = 16; o; o >>= 1) sum += __shfl_xor_sync(~0u, sum, o);
    float inv = 1.f / sum;
#pragma unroll
    for (int i = 0; i < 4; i++) {
        v[i].x *= inv; v[i].y *= inv; v[i].z *= inv; v[i].w *= inv;
        *(float4*)(p + i * 128 + lane * 4) = v[i];
    }
}

// ================= V transpose: g_vt[bh][d][s] = g_v[b,s,h*64+d] ============
__global__ void vtrans_kernel() {
    __shared__ float t[32][33];
    int bh = blockIdx.z, b = bh >> 3, h = bh & 7;
    int s0 = blockIdx.x * 32, d0 = blockIdx.y * 32;
    int tx = threadIdx.x, ty = threadIdx.y;
#pragma unroll
    for (int i = 0; i < 32; i += 8)
        t[ty + i][tx] = g_v[(size_t)(b * S_ + s0 + ty + i) * DM_ + h * 64 + d0 + tx];
    __syncthreads();
#pragma unroll
    for (int i = 0; i < 32; i += 8)
        g_vt[(size_t)bh * (DK_ * S_) + (d0 + ty + i) * S_ + s0 + tx] = t[tx][ty + i];
}

// ================= final: gate * fc + residual + LayerNorm ==================
__global__ void final_kernel(const float* __restrict__ xs,
                             const float* __restrict__ lng,
                             const float* __restrict__ lnb,
                             float* __restrict__ out) {
    int row = blockIdx.x;
    int b = row >> 10;
    int l = row & 1023;
    int s = l & (S_ - 1);
    int d1 = threadIdx.x, d2 = threadIdx.x + 256;
    size_t ro = (size_t)row * DM_;
    size_t go = (size_t)(b * S_ + s) * DM_;
    float v1 = xs[ro + d1] + g_gamma[go + d1] * g_fc[ro + d1];
    float v2 = xs[ro + d2] + g_gamma[go + d2] * g_fc[ro + d2];
    float sum = v1 + v2, sq = v1 * v1 + v2 * v2;
#pragma unroll
    for (int o = 16; o; o >>= 1) {
        sum += __shfl_xor_sync(0xffffffffu, sum, o);
        sq  += __shfl_xor_sync(0xffffffffu, sq,  o);
    }
    __shared__ float rs[8], rq[8];
    int w = threadIdx.x >> 5, lane = threadIdx.x & 31;
    if (lane == 0) { rs[w] = sum; rq[w] = sq; }
    __syncthreads();
    float tsum = 0.f, tsq = 0.f;
#pragma unroll
    for (int i = 0; i < 8; i++) { tsum += rs[i]; tsq += rq[i]; }
    float mu = tsum * (1.f / DM_);
    float var = tsq * (1.f / DM_) - mu * mu;
    float inv = rsqrtf(var + 1e-5f);
    out[ro + d1] = (v1 - mu) * inv * lng[d1] + lnb[d1];
    out[ro + d2] = (v2 - mu) * inv * lng[d2] + lnb[d2];
}

// ================= launch =================
extern "C" void kernel_launch(void* const* d_in, const int* in_sizes, int n_in,
                              void* d_out, int out_size) {
    const float* x_spatial  = (const float*)d_in[0];
    const float* x_velocity = (const float*)d_in[1];
    const float* w_gamma    = (const float*)d_in[2];
    const float* w3 = (const float*)d_in[3];  const float* b3 = (const float*)d_in[4];
    const float* w5 = (const float*)d_in[5];  const float* b5 = (const float*)d_in[6];
    const float* w7 = (const float*)d_in[7];  const float* b7 = (const float*)d_in[8];
    const float* rel = (const float*)d_in[9];
    const float* dww = (const float*)d_in[10]; const float* dwb = (const float*)d_in[11];
    const float* wq  = (const float*)d_in[12];
    const float* wk  = (const float*)d_in[13];
    const float* wv  = (const float*)d_in[14];
    const float* fcw = (const float*)d_in[15]; const float* fcb = (const float*)d_in[16];
    const float* lng = (const float*)d_in[17]; const float* lnb = (const float*)d_in[18];
    float* out = (float*)d_out;

    float *p_gamma, *p_q, *p_k, *p_v, *p_vt, *p_sc, *p_att, *p_fc, *p_xpe;
    cudaGetSymbolAddress((void**)&p_gamma, g_gamma);
    cudaGetSymbolAddress((void**)&p_q,     g_q);
    cudaGetSymbolAddress((void**)&p_k,     g_k);
    cudaGetSymbolAddress((void**)&p_v,     g_v);
    cudaGetSymbolAddress((void**)&p_vt,    g_vt);
    cudaGetSymbolAddress((void**)&p_sc,    g_scores);
    cudaGetSymbolAddress((void**)&p_att,   g_att);
    cudaGetSymbolAddress((void**)&p_fc,    g_fc);
    cudaGetSymbolAddress((void**)&p_xpe,   g_xpe);

    // 1-3: prologue
    mean_rel_kernel<<<S_, D3_>>>(rel);
    conv_kernel<<<dim3(B_, S_ / 32), D3_>>>(x_velocity, w3, b3, w5, b5, w7, b7);
    xpe_kernel<<<B_ * S_, D3_>>>(rel, dww, dwb);

    // 4: gamma = sigmoid(xv @ w_gamma^T)     M=4096 N=512 K=64
    mma_gemm<128, 1><<<dim3(4, 32, 1), 256>>>(
        x_velocity, w_gamma, nullptr, p_gamma, 64, 64, 64, DM_, 0,0,0,0,0,0);
    // 5: q = x_spatial @ wq^T                M=8192 N=512 K=512
    mma_gemm<128, 0><<<dim3(4, 64, 1), 256>>>(
        x_spatial, wq, nullptr, p_q, SD_, SD_, SD_, DM_, 0,0,0,0,0,0);
    // 6/7: k, v = x_pe @ wk^T / wv^T         M=4096 N=512 K=192
    mma_gemm<128, 0><<<dim3(4, 32, 1), 256>>>(
        p_xpe, wk, nullptr, p_k, D3_, D3_, D3_, DM_, 0,0,0,0,0,0);
    mma_gemm<128, 0><<<dim3(4, 32, 1), 256>>>(
        p_xpe, wv, nullptr, p_v, D3_, D3_, D3_, DM_, 0,0,0,0,0,0);
    // 8: scores[b,h,l,s] = q . k             batched, M=1024 N=512 K=64
    mma_gemm<128, 0><<<dim3(4, 8, BH_), 256>>>(
        p_q, p_k, nullptr, p_sc, DK_, DM_, DM_, S_,
        (long long)L_ * DM_, 64,
        (long long)S_ * DM_, 64,
        (long long)NH_ * L_ * S_, (long long)L_ * S_);
    // 9: softmax (1/8 scale folded in), in place
    softmax_kernel<<<BH_ * L_ / 8, 256>>>();
    // 10: V transpose for PV GEMM
    vtrans_kernel<<<dim3(S_ / 32, DK_ / 32, BH_), dim3(32, 8)>>>();
    // 11: att[b,l,h*64+d] = P @ V            batched, M=1024 N=64 K=512
    mma_gemm<64, 0><<<dim3(1, 8, BH_), 256>>>(
        p_sc, p_vt, nullptr, p_att, S_, S_, S_, DM_,
        (long long)NH_ * L_ * S_, (long long)L_ * S_,
        (long long)NH_ * DK_ * S_, (long long)DK_ * S_,
        (long long)L_ * DM_, 64);
    // 12: fc = att @ fc_w^T + fc_b           M=8192 N=512 K=512
    mma_gemm<128, 2><<<dim3(4, 64, 1), 256>>>(
        p_att, fcw, fcb, p_fc, DM_, DM_, DM_, DM_, 0,0,0,0,0,0);
    // 13: gate + residual + layernorm
    final_kernel<<<B_ * L_, 256>>>(x_spatial, lng, lnb, out);
}

// round 5
// speedup vs baseline: 3.2706x; 1.1682x over previous
#include <cuda_runtime.h>
#include <math.h>
#include <stdint.h>

#define B_  8
#define L_  1024
#define S_  512
#define SD_ 512
#define VD_ 64
#define DM_ 512
#define D3_ 192
#define NH_ 8
#define DK_ 64
#define BH_ (B_ * NH_)

// ---------------- scratch (device globals; no allocation) ----------------
__device__ float g_mean_rel[S_ * D3_];
__device__ float g_ms    [B_ * S_ * D3_];
__device__ float g_xpe   [B_ * S_ * D3_];
__device__ float g_gamma [B_ * S_ * DM_];
__device__ float g_q     [B_ * L_ * DM_];
__device__ float g_k     [B_ * S_ * DM_];
__device__ float g_v     [B_ * S_ * DM_];
__device__ float g_att   [B_ * L_ * DM_];
__device__ float g_fc    [B_ * L_ * DM_];

// ---------------- tf32 helpers ----------------
__device__ __forceinline__ uint32_t f2tf(float x) {
    uint32_t r;
    asm("cvt.rna.tf32.f32 %0, %1;" : "=r"(r) : "f"(x));
    return r;
}
__device__ __forceinline__ void mma_tf32(float* c, const uint32_t* a, const uint32_t* b) {
    asm volatile(
        "mma.sync.aligned.m16n8k8.row.col.f32.tf32.tf32.f32 "
        "{%0,%1,%2,%3}, {%4,%5,%6,%7}, {%8,%9}, {%0,%1,%2,%3};\n"
        : "+f"(c[0]), "+f"(c[1]), "+f"(c[2]), "+f"(c[3])
        : "r"(a[0]), "r"(a[1]), "r"(a[2]), "r"(a[3]), "r"(b[0]), "r"(b[1]));
}

// ================= K1: mean_rel =================
__global__ void mean_rel_kernel(const float* __restrict__ rel) {
    __shared__ float srel[61 * D3_];
    for (int i = threadIdx.x; i < 61 * D3_; i += blockDim.x) srel[i] = rel[i];
    __syncthreads();
    int j = blockIdx.x, d = threadIdx.x;
    float sum = 0.f;
    for (int i = 0; i < S_; i++) {
        int r = j - i;
        r = min(30, max(-30, r)) + 30;
        sum += srel[r * D3_ + d];
    }
    g_mean_rel[j * D3_ + d] = sum * (1.f / S_);
}

// ================= K2: multi-scale convs =================
template <int KW>
__device__ __forceinline__ void conv_body(const float (*sx)[VD_],
                                          const float* __restrict__ w,
                                          float bias, float* acc) {
#pragma unroll
    for (int s = 0; s < 32; s++) acc[s] = bias;
    const int off0 = 3 - KW / 2;
    for (int cin = 0; cin < VD_; cin++) {
#pragma unroll
        for (int t = 0; t < KW; t++) {
            float wv = __ldg(w + cin * KW + t);
#pragma unroll
            for (int s = 0; s < 32; s++)
                acc[s] = fmaf(wv, sx[s + off0 + t][cin], acc[s]);
        }
    }
}

__global__ void conv_kernel(const float* __restrict__ xv,
                            const float* __restrict__ w3, const float* __restrict__ b3,
                            const float* __restrict__ w5, const float* __restrict__ b5,
                            const float* __restrict__ w7, const float* __restrict__ b7) {
    int b = blockIdx.x, s0 = blockIdx.y * 32;
    __shared__ float sx[38][VD_];
    for (int idx = threadIdx.x; idx < 38 * VD_; idx += 192) {
        int r = idx >> 6, cin = idx & 63;
        int s = s0 + r - 3;
        sx[r][cin] = ((unsigned)s < S_) ? xv[(b * S_ + s) * VD_ + cin] : 0.f;
    }
    __syncthreads();
    int c = threadIdx.x;
    float acc[32];
    if (c < 64)       conv_body<3>(sx, w3 + c * 64 * 3,         b3[c],        acc);
    else if (c < 128) conv_body<5>(sx, w5 + (c - 64) * 64 * 5,  b5[c - 64],   acc);
    else              conv_body<7>(sx, w7 + (c - 128) * 64 * 7, b7[c - 128],  acc);
#pragma unroll
    for (int s = 0; s < 32; s++)
        g_ms[((b * S_) + s0 + s) * D3_ + c] = acc[s];
}

// ================= K3: x_pe =================
__global__ void xpe_kernel(const float* __restrict__ rel,
                           const float* __restrict__ dww,
                           const float* __restrict__ dwb) {
    int bs = blockIdx.x;
    int s = bs & (S_ - 1);
    int d = threadIdx.x;
    int base = bs * D3_ + d;
    float msv = g_ms[base];
    float center = msv + rel[30 * D3_ + d];
    float left  = (s > 0)      ? g_ms[base - D3_] + rel[29 * D3_ + d] : 0.f;
    float right = (s < S_ - 1) ? g_ms[base + D3_] + rel[31 * D3_ + d] : 0.f;
    float diag = dww[d * 3 + 0] * left + dww[d * 3 + 1] * center +
                 dww[d * 3 + 2] * right + dwb[d];
    g_xpe[base] = msv + g_mean_rel[s * D3_ + d] + (diag - center) * (1.f / S_);
}

// ================= tf32 mma.sync GEMM (projections) =================
// C[m,n] = sum_k A[m,k] * B[n,k]   (both K-major)
// EPI: 0 none, 1 sigmoid, 2 +bias
template <int NT, int EPI>
__global__ void __launch_bounds__(256) mma_gemm(
    const float* __restrict__ A, const float* __restrict__ Bw,
    const float* __restrict__ bias, float* __restrict__ C,
    int K, int lda, int ldb, int ldc)
{
    constexpr int WROWS = 2;
    constexpr int WM  = 64;
    constexpr int WN  = NT / 4;
    constexpr int MT  = WM / 16;
    constexpr int NTT = WN / 8;
    constexpr int AIT = 4;
    constexpr int BIT = NT / 32;

    __shared__ uint32_t As[128][36];
    __shared__ uint32_t Bs[NT][36];

    int tid = threadIdx.x;
    int wid = tid >> 5, lane = tid & 31;
    int wm = (wid % WROWS) * WM;
    int wn = (wid / WROWS) * WN;
    int lg = lane >> 2, lr = lane & 3;

    const float* Ap = A + (size_t)blockIdx.y * 128 * lda;
    const float* Bp = Bw + (size_t)blockIdx.x * NT * ldb;
    float* Cp = C + (size_t)blockIdx.y * 128 * ldc + blockIdx.x * NT;

    float acc[MT][NTT][4];
#pragma unroll
    for (int i = 0; i < MT; i++)
#pragma unroll
        for (int j = 0; j < NTT; j++)
#pragma unroll
            for (int q = 0; q < 4; q++) acc[i][j][q] = 0.f;

    float4 pa[AIT], pb[BIT];
    int nch = K >> 5;

#pragma unroll
    for (int i = 0; i < AIT; i++) {
        int idx = i * 256 + tid, r = idx >> 3, c4 = idx & 7;
        pa[i] = *(const float4*)(Ap + (size_t)r * lda + c4 * 4);
    }
#pragma unroll
    for (int i = 0; i < BIT; i++) {
        int idx = i * 256 + tid, r = idx >> 3, c4 = idx & 7;
        pb[i] = *(const float4*)(Bp + (size_t)r * ldb + c4 * 4);
    }

    for (int c = 0; c < nch; c++) {
#pragma unroll
        for (int i = 0; i < AIT; i++) {
            int idx = i * 256 + tid, r = idx >> 3, c4 = idx & 7;
            uint4 u = {f2tf(pa[i].x), f2tf(pa[i].y), f2tf(pa[i].z), f2tf(pa[i].w)};
            *(uint4*)&As[r][c4 * 4] = u;
        }
#pragma unroll
        for (int i = 0; i < BIT; i++) {
            int idx = i * 256 + tid, r = idx >> 3, c4 = idx & 7;
            uint4 u = {f2tf(pb[i].x), f2tf(pb[i].y), f2tf(pb[i].z), f2tf(pb[i].w)};
            *(uint4*)&Bs[r][c4 * 4] = u;
        }
        __syncthreads();
        if (c + 1 < nch) {
            int kc = (c + 1) * 32;
#pragma unroll
            for (int i = 0; i < AIT; i++) {
                int idx = i * 256 + tid, r = idx >> 3, c4 = idx & 7;
                pa[i] = *(const float4*)(Ap + (size_t)r * lda + kc + c4 * 4);
            }
#pragma unroll
            for (int i = 0; i < BIT; i++) {
                int idx = i * 256 + tid, r = idx >> 3, c4 = idx & 7;
                pb[i] = *(const float4*)(Bp + (size_t)r * ldb + kc + c4 * 4);
            }
        }
#pragma unroll
        for (int kk = 0; kk < 32; kk += 8) {
            uint32_t af[MT][4], bf[NTT][2];
#pragma unroll
            for (int mt = 0; mt < MT; mt++) {
                int r = wm + mt * 16 + lg;
                af[mt][0] = As[r][kk + lr];
                af[mt][1] = As[r + 8][kk + lr];
                af[mt][2] = As[r][kk + lr + 4];
                af[mt][3] = As[r + 8][kk + lr + 4];
            }
#pragma unroll
            for (int nt = 0; nt < NTT; nt++) {
                int r = wn + nt * 8 + lg;
                bf[nt][0] = Bs[r][kk + lr];
                bf[nt][1] = Bs[r][kk + lr + 4];
            }
#pragma unroll
            for (int mt = 0; mt < MT; mt++)
#pragma unroll
                for (int nt = 0; nt < NTT; nt++)
                    mma_tf32(acc[mt][nt], af[mt], bf[nt]);
        }
        __syncthreads();
    }

    int n0 = blockIdx.x * NT;
#pragma unroll
    for (int mt = 0; mt < MT; mt++) {
#pragma unroll
        for (int nt = 0; nt < NTT; nt++) {
            int r = wm + mt * 16 + lg;
            int cc = wn + nt * 8 + lr * 2;
            float v0 = acc[mt][nt][0], v1 = acc[mt][nt][1];
            float v2 = acc[mt][nt][2], v3 = acc[mt][nt][3];
            if (EPI == 1) {
                v0 = 1.f / (1.f + __expf(-v0));
                v1 = 1.f / (1.f + __expf(-v1));
                v2 = 1.f / (1.f + __expf(-v2));
                v3 = 1.f / (1.f + __expf(-v3));
            }
            if (EPI == 2) {
                float b0 = bias[n0 + cc], b1 = bias[n0 + cc + 1];
                v0 += b0; v1 += b1; v2 += b0; v3 += b1;
            }
            *(float2*)(Cp + (size_t)r * ldc + cc) = make_float2(v0, v1);
            *(float2*)(Cp + (size_t)(r + 8) * ldc + cc) = make_float2(v2, v3);
        }
    }
}

// ================= fused flash attention =================
// CTA: 128 Q rows x one (b,h). 8 warps, each owns 16 rows (softmax warp-local).
// KV chunks of 64; V consumed K-major directly (no transpose).
// smem: region0 = Q tile (128x68) then reused as per-warp P slices; K 64x68; V 64x68
#define FLASH_SMEM ((128 * 68 + 2 * 64 * 68) * 4)

__global__ void __launch_bounds__(256) flash_kernel() {
    extern __shared__ float fs[];
    float* Ps = fs;                  // 128 x 68 (Q, then P)
    float* Ks = fs + 128 * 68;       // 64 x 68
    float* Vs = Ks + 64 * 68;        // 64 x 68

    int tid = threadIdx.x;
    int wid = tid >> 5, lane = tid & 31;
    int lg = lane >> 2, lr = lane & 3;
    int bh = blockIdx.y, b = bh >> 3, h = bh & 7;
    int l0 = blockIdx.x * 128;

    const float* Qp = g_q + (size_t)(b * L_ + l0) * DM_ + h * 64;
    const float* Kp = g_k + (size_t)(b * S_) * DM_ + h * 64;
    const float* Vp = g_v + (size_t)(b * S_) * DM_ + h * 64;

    // ---- load Q tile (scaled by 1/8, tf32) ----
#pragma unroll
    for (int i = 0; i < 8; i++) {
        int idx = i * 256 + tid, r = idx >> 4, c4 = (idx & 15) * 4;
        float4 v = *(const float4*)(Qp + (size_t)r * DM_ + c4);
        uint32_t* dst = (uint32_t*)&Ps[r * 68 + c4];
        dst[0] = f2tf(v.x * 0.125f); dst[1] = f2tf(v.y * 0.125f);
        dst[2] = f2tf(v.z * 0.125f); dst[3] = f2tf(v.w * 0.125f);
    }
    __syncthreads();

    // ---- Q fragments (warp's 16 rows) ----
    uint32_t qf[8][4];
    {
        int r = wid * 16 + lg;
#pragma unroll
        for (int kk = 0; kk < 8; kk++) {
            qf[kk][0] = ((uint32_t*)Ps)[r * 68 + kk * 8 + lr];
            qf[kk][1] = ((uint32_t*)Ps)[(r + 8) * 68 + kk * 8 + lr];
            qf[kk][2] = ((uint32_t*)Ps)[r * 68 + kk * 8 + lr + 4];
            qf[kk][3] = ((uint32_t*)Ps)[(r + 8) * 68 + kk * 8 + lr + 4];
        }
    }
    __syncthreads();
    float* Pw = Ps + wid * 16 * 68;   // warp's private P slice (rows wid*16..+15)
    uint32_t* Pwu = (uint32_t*)Pw;

    float m0 = -1e30f, m1 = -1e30f, l0s = 0.f, l1s = 0.f;
    float o[8][4];
#pragma unroll
    for (int nt = 0; nt < 8; nt++)
#pragma unroll
        for (int q = 0; q < 4; q++) o[nt][q] = 0.f;

    // prefetch chunk 0
    float4 pk[4], pv[4];
#pragma unroll
    for (int i = 0; i < 4; i++) {
        int idx = i * 256 + tid, r = idx >> 4, c4 = (idx & 15) * 4;
        pk[i] = *(const float4*)(Kp + (size_t)r * DM_ + c4);
        pv[i] = *(const float4*)(Vp + (size_t)r * DM_ + c4);
    }

    for (int sc = 0; sc < 8; sc++) {
        // store chunk (tf32)
#pragma unroll
        for (int i = 0; i < 4; i++) {
            int idx = i * 256 + tid, r = idx >> 4, c4 = (idx & 15) * 4;
            uint32_t* dk = (uint32_t*)&Ks[r * 68 + c4];
            dk[0] = f2tf(pk[i].x); dk[1] = f2tf(pk[i].y);
            dk[2] = f2tf(pk[i].z); dk[3] = f2tf(pk[i].w);
            uint32_t* dv = (uint32_t*)&Vs[r * 68 + c4];
            dv[0] = f2tf(pv[i].x); dv[1] = f2tf(pv[i].y);
            dv[2] = f2tf(pv[i].z); dv[3] = f2tf(pv[i].w);
        }
        __syncthreads();
        if (sc + 1 < 8) {
            const float* Kn = Kp + (size_t)(sc + 1) * 64 * DM_;
            const float* Vn = Vp + (size_t)(sc + 1) * 64 * DM_;
#pragma unroll
            for (int i = 0; i < 4; i++) {
                int idx = i * 256 + tid, r = idx >> 4, c4 = (idx & 15) * 4;
                pk[i] = *(const float4*)(Kn + (size_t)r * DM_ + c4);
                pv[i] = *(const float4*)(Vn + (size_t)r * DM_ + c4);
            }
        }

        // ---- S = Q . K^T  (warp: 16 x 64) ----
        float s[8][4];
#pragma unroll
        for (int nt = 0; nt < 8; nt++)
#pragma unroll
            for (int q = 0; q < 4; q++) s[nt][q] = 0.f;
#pragma unroll
        for (int kk = 0; kk < 8; kk++) {
            uint32_t bf[8][2];
#pragma unroll
            for (int nt = 0; nt < 8; nt++) {
                int r = nt * 8 + lg;
                bf[nt][0] = ((uint32_t*)Ks)[r * 68 + kk * 8 + lr];
                bf[nt][1] = ((uint32_t*)Ks)[r * 68 + kk * 8 + lr + 4];
            }
#pragma unroll
            for (int nt = 0; nt < 8; nt++)
                mma_tf32(s[nt], qf[kk], bf[nt]);
        }

        // ---- online softmax update (rows lg and lg+8 of warp tile) ----
        float cm0 = -1e30f, cm1 = -1e30f;
#pragma unroll
        for (int nt = 0; nt < 8; nt++) {
            cm0 = fmaxf(cm0, fmaxf(s[nt][0], s[nt][1]));
            cm1 = fmaxf(cm1, fmaxf(s[nt][2], s[nt][3]));
        }
        cm0 = fmaxf(cm0, __shfl_xor_sync(~0u, cm0, 1));
        cm0 = fmaxf(cm0, __shfl_xor_sync(~0u, cm0, 2));
        cm1 = fmaxf(cm1, __shfl_xor_sync(~0u, cm1, 1));
        cm1 = fmaxf(cm1, __shfl_xor_sync(~0u, cm1, 2));
        float nm0 = fmaxf(m0, cm0), nm1 = fmaxf(m1, cm1);
        float a0 = __expf(m0 - nm0), a1 = __expf(m1 - nm1);
        float rs0 = 0.f, rs1 = 0.f;
#pragma unroll
        for (int nt = 0; nt < 8; nt++) {
            float p0 = __expf(s[nt][0] - nm0);
            float p1 = __expf(s[nt][1] - nm0);
            float p2 = __expf(s[nt][2] - nm1);
            float p3 = __expf(s[nt][3] - nm1);
            rs0 += p0 + p1; rs1 += p2 + p3;
            int cbase = nt * 8 + 2 * lr;
            Pwu[lg * 68 + cbase]       = f2tf(p0);
            Pwu[lg * 68 + cbase + 1]   = f2tf(p1);
            Pwu[(lg + 8) * 68 + cbase]     = f2tf(p2);
            Pwu[(lg + 8) * 68 + cbase + 1] = f2tf(p3);
        }
        rs0 += __shfl_xor_sync(~0u, rs0, 1); rs0 += __shfl_xor_sync(~0u, rs0, 2);
        rs1 += __shfl_xor_sync(~0u, rs1, 1); rs1 += __shfl_xor_sync(~0u, rs1, 2);
        l0s = l0s * a0 + rs0; l1s = l1s * a1 + rs1;
        m0 = nm0; m1 = nm1;
#pragma unroll
        for (int nt = 0; nt < 8; nt++) {
            o[nt][0] *= a0; o[nt][1] *= a0;
            o[nt][2] *= a1; o[nt][3] *= a1;
        }
        __syncwarp();

        // ---- O += P . V  (k = chunk 64, V read K-major: b = V[k][n]) ----
#pragma unroll
        for (int kk = 0; kk < 8; kk++) {
            uint32_t pf[4];
            pf[0] = Pwu[lg * 68 + kk * 8 + lr];
            pf[1] = Pwu[(lg + 8) * 68 + kk * 8 + lr];
            pf[2] = Pwu[lg * 68 + kk * 8 + lr + 4];
            pf[3] = Pwu[(lg + 8) * 68 + kk * 8 + lr + 4];
            uint32_t bf[8][2];
#pragma unroll
            for (int nt = 0; nt < 8; nt++) {
                bf[nt][0] = ((uint32_t*)Vs)[(kk * 8 + lr) * 68 + nt * 8 + lg];
                bf[nt][1] = ((uint32_t*)Vs)[(kk * 8 + lr + 4) * 68 + nt * 8 + lg];
            }
#pragma unroll
            for (int nt = 0; nt < 8; nt++)
                mma_tf32(o[nt], pf, bf[nt]);
        }
        __syncthreads();
    }

    // ---- finalize: O / l, write out ----
    float inv0 = 1.f / l0s, inv1 = 1.f / l1s;
    int orow = l0 + wid * 16 + lg;
    float* Op = g_att + (size_t)(b * L_ + orow) * DM_ + h * 64;
#pragma unroll
    for (int nt = 0; nt < 8; nt++) {
        int cc = nt * 8 + 2 * lr;
        *(float2*)(Op + cc) = make_float2(o[nt][0] * inv0, o[nt][1] * inv0);
        *(float2*)(Op + 8 * DM_ + cc) = make_float2(o[nt][2] * inv1, o[nt][3] * inv1);
    }
}

// ================= final: gate * fc + residual + LayerNorm ==================
__global__ void final_kernel(const float* __restrict__ xs,
                             const float* __restrict__ lng,
                             const float* __restrict__ lnb,
                             float* __restrict__ out) {
    int row = blockIdx.x;
    int b = row >> 10;
    int l = row & 1023;
    int s = l & (S_ - 1);
    int d1 = threadIdx.x, d2 = threadIdx.x + 256;
    size_t ro = (size_t)row * DM_;
    size_t go = (size_t)(b * S_ + s) * DM_;
    float v1 = xs[ro + d1] + g_gamma[go + d1] * g_fc[ro + d1];
    float v2 = xs[ro + d2] + g_gamma[go + d2] * g_fc[ro + d2];
    float sum = v1 + v2, sq = v1 * v1 + v2 * v2;
#pragma unroll
    for (int o = 16; o; o >>= 1) {
        sum += __shfl_xor_sync(0xffffffffu, sum, o);
        sq  += __shfl_xor_sync(0xffffffffu, sq,  o);
    }
    __shared__ float rs[8], rq[8];
    int w = threadIdx.x >> 5, lane = threadIdx.x & 31;
    if (lane == 0) { rs[w] = sum; rq[w] = sq; }
    __syncthreads();
    float tsum = 0.f, tsq = 0.f;
#pragma unroll
    for (int i = 0; i < 8; i++) { tsum += rs[i]; tsq += rq[i]; }
    float mu = tsum * (1.f / DM_);
    float var = tsq * (1.f / DM_) - mu * mu;
    float inv = rsqrtf(var + 1e-5f);
    out[ro + d1] = (v1 - mu) * inv * lng[d1] + lnb[d1];
    out[ro + d2] = (v2 - mu) * inv * lng[d2] + lnb[d2];
}

// ================= launch =================
extern "C" void kernel_launch(void* const* d_in, const int* in_sizes, int n_in,
                              void* d_out, int out_size) {
    const float* x_spatial  = (const float*)d_in[0];
    const float* x_velocity = (const float*)d_in[1];
    const float* w_gamma    = (const float*)d_in[2];
    const float* w3 = (const float*)d_in[3];  const float* b3 = (const float*)d_in[4];
    const float* w5 = (const float*)d_in[5];  const float* b5 = (const float*)d_in[6];
    const float* w7 = (const float*)d_in[7];  const float* b7 = (const float*)d_in[8];
    const float* rel = (const float*)d_in[9];
    const float* dww = (const float*)d_in[10]; const float* dwb = (const float*)d_in[11];
    const float* wq  = (const float*)d_in[12];
    const float* wk  = (const float*)d_in[13];
    const float* wv  = (const float*)d_in[14];
    const float* fcw = (const float*)d_in[15]; const float* fcb = (const float*)d_in[16];
    const float* lng = (const float*)d_in[17]; const float* lnb = (const float*)d_in[18];
    float* out = (float*)d_out;

    float *p_gamma, *p_q, *p_k, *p_v, *p_att, *p_fc, *p_xpe;
    cudaGetSymbolAddress((void**)&p_gamma, g_gamma);
    cudaGetSymbolAddress((void**)&p_q,     g_q);
    cudaGetSymbolAddress((void**)&p_k,     g_k);
    cudaGetSymbolAddress((void**)&p_v,     g_v);
    cudaGetSymbolAddress((void**)&p_att,   g_att);
    cudaGetSymbolAddress((void**)&p_fc,    g_fc);
    cudaGetSymbolAddress((void**)&p_xpe,   g_xpe);

    cudaFuncSetAttribute(flash_kernel,
                         cudaFuncAttributeMaxDynamicSharedMemorySize, FLASH_SMEM);

    // 1-3: prologue
    mean_rel_kernel<<<S_, D3_>>>(rel);
    conv_kernel<<<dim3(B_, S_ / 32), D3_>>>(x_velocity, w3, b3, w5, b5, w7, b7);
    xpe_kernel<<<B_ * S_, D3_>>>(rel, dww, dwb);

    // 4: gamma = sigmoid(xv @ w_gamma^T)     M=4096 N=512 K=64
    mma_gemm<128, 1><<<dim3(4, 32), 256>>>(
        x_velocity, w_gamma, nullptr, p_gamma, 64, 64, 64, DM_);
    // 5: q = x_spatial @ wq^T                M=8192 N=512 K=512
    mma_gemm<128, 0><<<dim3(4, 64), 256>>>(
        x_spatial, wq, nullptr, p_q, SD_, SD_, SD_, DM_);
    // 6/7: k, v = x_pe @ wk^T / wv^T         M=4096 N=512 K=192
    mma_gemm<128, 0><<<dim3(4, 32), 256>>>(
        p_xpe, wk, nullptr, p_k, D3_, D3_, D3_, DM_);
    mma_gemm<128, 0><<<dim3(4, 32), 256>>>(
        p_xpe, wv, nullptr, p_v, D3_, D3_, D3_, DM_);
    // 8: fused flash attention -> g_att
    flash_kernel<<<dim3(L_ / 128, BH_), 256, FLASH_SMEM>>>();
    // 9: fc = att @ fc_w^T + fc_b            M=8192 N=512 K=512
    mma_gemm<128, 2><<<dim3(4, 64), 256>>>(
        p_att, fcw, fcb, p_fc, DM_, DM_, DM_, DM_);
    // 10: gate + residual + layernorm
    final_kernel<<<B_ * L_, 256>>>(x_spatial, lng, lnb, out);
}

// round 6
// speedup vs baseline: 3.4568x; 1.0569x over previous
#include <cuda_runtime.h>
#include <math.h>
#include <stdint.h>

#define B_  8
#define L_  1024
#define S_  512
#define SD_ 512
#define VD_ 64
#define DM_ 512
#define D3_ 192
#define NH_ 8
#define DK_ 64
#define BH_ (B_ * NH_)

// ---------------- scratch (device globals; no allocation) ----------------
__device__ float g_mean_rel[S_ * D3_];
__device__ float g_ms    [B_ * S_ * D3_];
__device__ float g_xpe   [B_ * S_ * D3_];
__device__ float g_gamma [B_ * S_ * DM_];
__device__ float g_q     [B_ * L_ * DM_];
__device__ float g_k     [B_ * S_ * DM_];
__device__ float g_v     [B_ * S_ * DM_];
__device__ float g_att   [B_ * L_ * DM_];
__device__ float g_fc    [B_ * L_ * DM_];

// ---------------- helpers ----------------
__device__ __forceinline__ uint32_t s2u(const void* p) {
    uint32_t a;
    asm("{ .reg .u64 t; cvta.to.shared.u64 t, %1; cvt.u32.u64 %0, t; }"
        : "=r"(a) : "l"(p));
    return a;
}
__device__ __forceinline__ void cpa16(uint32_t dst, const void* src) {
    asm volatile("cp.async.cg.shared.global [%0], [%1], 16;" :: "r"(dst), "l"(src));
}
#define CPA_COMMIT() asm volatile("cp.async.commit_group;" ::: "memory")
#define CPA_WAIT0()  asm volatile("cp.async.wait_group 0;" ::: "memory")
#define CPA_WAIT1()  asm volatile("cp.async.wait_group 1;" ::: "memory")
#define CPA_WAIT2()  asm volatile("cp.async.wait_group 2;" ::: "memory")

__device__ __forceinline__ void mma_tf32(float* c, const uint32_t* a, const uint32_t* b) {
    asm volatile(
        "mma.sync.aligned.m16n8k8.row.col.f32.tf32.tf32.f32 "
        "{%0,%1,%2,%3}, {%4,%5,%6,%7}, {%8,%9}, {%0,%1,%2,%3};\n"
        : "+f"(c[0]), "+f"(c[1]), "+f"(c[2]), "+f"(c[3])
        : "r"(a[0]), "r"(a[1]), "r"(a[2]), "r"(a[3]), "r"(b[0]), "r"(b[1]));
}

// ================= K1: mean_rel =================
__global__ void mean_rel_kernel(const float* __restrict__ rel) {
    __shared__ float srel[61 * D3_];
    for (int i = threadIdx.x; i < 61 * D3_; i += blockDim.x) srel[i] = rel[i];
    __syncthreads();
    int j = blockIdx.x, d = threadIdx.x;
    float sum = 0.f;
    for (int i = 0; i < S_; i++) {
        int r = j - i;
        r = min(30, max(-30, r)) + 30;
        sum += srel[r * D3_ + d];
    }
    g_mean_rel[j * D3_ + d] = sum * (1.f / S_);
}

// ================= K2: multi-scale convs =================
template <int KW>
__device__ __forceinline__ void conv_body(const float (*sx)[VD_],
                                          const float* __restrict__ w,
                                          float bias, float* acc) {
#pragma unroll
    for (int s = 0; s < 32; s++) acc[s] = bias;
    const int off0 = 3 - KW / 2;
    for (int cin = 0; cin < VD_; cin++) {
#pragma unroll
        for (int t = 0; t < KW; t++) {
            float wv = __ldg(w + cin * KW + t);
#pragma unroll
            for (int s = 0; s < 32; s++)
                acc[s] = fmaf(wv, sx[s + off0 + t][cin], acc[s]);
        }
    }
}

__global__ void conv_kernel(const float* __restrict__ xv,
                            const float* __restrict__ w3, const float* __restrict__ b3,
                            const float* __restrict__ w5, const float* __restrict__ b5,
                            const float* __restrict__ w7, const float* __restrict__ b7) {
    int b = blockIdx.x, s0 = blockIdx.y * 32;
    __shared__ float sx[38][VD_];
    for (int idx = threadIdx.x; idx < 38 * VD_; idx += 192) {
        int r = idx >> 6, cin = idx & 63;
        int s = s0 + r - 3;
        sx[r][cin] = ((unsigned)s < S_) ? xv[(b * S_ + s) * VD_ + cin] : 0.f;
    }
    __syncthreads();
    int c = threadIdx.x;
    float acc[32];
    if (c < 64)       conv_body<3>(sx, w3 + c * 64 * 3,         b3[c],        acc);
    else if (c < 128) conv_body<5>(sx, w5 + (c - 64) * 64 * 5,  b5[c - 64],   acc);
    else              conv_body<7>(sx, w7 + (c - 128) * 64 * 7, b7[c - 128],  acc);
#pragma unroll
    for (int s = 0; s < 32; s++)
        g_ms[((b * S_) + s0 + s) * D3_ + c] = acc[s];
}

// ================= K3: x_pe =================
__global__ void xpe_kernel(const float* __restrict__ rel,
                           const float* __restrict__ dww,
                           const float* __restrict__ dwb) {
    int bs = blockIdx.x;
    int s = bs & (S_ - 1);
    int d = threadIdx.x;
    int base = bs * D3_ + d;
    float msv = g_ms[base];
    float center = msv + rel[30 * D3_ + d];
    float left  = (s > 0)      ? g_ms[base - D3_] + rel[29 * D3_ + d] : 0.f;
    float right = (s < S_ - 1) ? g_ms[base + D3_] + rel[31 * D3_ + d] : 0.f;
    float diag = dww[d * 3 + 0] * left + dww[d * 3 + 1] * center +
                 dww[d * 3 + 2] * right + dwb[d];
    g_xpe[base] = msv + g_mean_rel[s * D3_ + d] + (diag - center) * (1.f / S_);
}

// ================= tf32 mma.sync GEMM (cp.async double-buffered) ===========
// C[m,n] = sum_k A[m,k] * B[n,k]   (both K-major, raw fp32 as tf32)
// EPI: 0 none, 1 sigmoid, 2 +bias
#define SMG ((2 * 128 * 36 + 2 * 128 * 36) * 4)

template <int NT, int EPI>
__global__ void __launch_bounds__(256, 2) mma_gemm(
    const float* __restrict__ A, const float* __restrict__ Bw,
    const float* __restrict__ bias, float* __restrict__ C,
    int K, int lda, int ldb, int ldc)
{
    constexpr int MT  = 4;          // 64-row warp tile
    constexpr int NTT = NT / 32;    // 32-col warp tile
    constexpr int AIT = 4;
    constexpr int BIT = NT / 32;

    extern __shared__ float gsm[];
    float* Ab[2] = {gsm, gsm + 128 * 36};
    float* Bb[2] = {gsm + 2 * 128 * 36, gsm + 2 * 128 * 36 + NT * 36};

    int tid = threadIdx.x;
    int wid = tid >> 5, lane = tid & 31;
    int wm = (wid & 1) * 64;
    int wn = (wid >> 1) * (NT / 4);
    int lg = lane >> 2, lr = lane & 3;

    const float* Ap = A + (size_t)blockIdx.y * 128 * lda;
    const float* Bp = Bw + (size_t)blockIdx.x * NT * ldb;
    float* Cp = C + (size_t)blockIdx.y * 128 * ldc + blockIdx.x * NT;

    int nch = K >> 5;

    auto issue = [&](int c) {
        int kc = c * 32;
        float* sa = Ab[c & 1];
        float* sb = Bb[c & 1];
#pragma unroll
        for (int i = 0; i < AIT; i++) {
            int idx = i * 256 + tid, r = idx >> 3, c4 = idx & 7;
            cpa16(s2u(sa + r * 36 + c4 * 4), Ap + (size_t)r * lda + kc + c4 * 4);
        }
#pragma unroll
        for (int i = 0; i < BIT; i++) {
            int idx = i * 256 + tid, r = idx >> 3, c4 = idx & 7;
            cpa16(s2u(sb + r * 36 + c4 * 4), Bp + (size_t)r * ldb + kc + c4 * 4);
        }
        CPA_COMMIT();
    };

    float acc[MT][NTT][4];
#pragma unroll
    for (int i = 0; i < MT; i++)
#pragma unroll
        for (int j = 0; j < NTT; j++)
#pragma unroll
            for (int q = 0; q < 4; q++) acc[i][j][q] = 0.f;

    issue(0);
    if (nch > 1) issue(1);

    for (int c = 0; c < nch; c++) {
        if (c < nch - 1) { CPA_WAIT1(); } else { CPA_WAIT0(); }
        __syncthreads();
        const uint32_t* As = (const uint32_t*)Ab[c & 1];
        const uint32_t* Bs = (const uint32_t*)Bb[c & 1];
#pragma unroll
        for (int kk = 0; kk < 32; kk += 8) {
            uint32_t af[MT][4], bf[NTT][2];
#pragma unroll
            for (int mt = 0; mt < MT; mt++) {
                int r = wm + mt * 16 + lg;
                af[mt][0] = As[r * 36 + kk + lr];
                af[mt][1] = As[(r + 8) * 36 + kk + lr];
                af[mt][2] = As[r * 36 + kk + lr + 4];
                af[mt][3] = As[(r + 8) * 36 + kk + lr + 4];
            }
#pragma unroll
            for (int nt = 0; nt < NTT; nt++) {
                int r = wn + nt * 8 + lg;
                bf[nt][0] = Bs[r * 36 + kk + lr];
                bf[nt][1] = Bs[r * 36 + kk + lr + 4];
            }
#pragma unroll
            for (int mt = 0; mt < MT; mt++)
#pragma unroll
                for (int nt = 0; nt < NTT; nt++)
                    mma_tf32(acc[mt][nt], af[mt], bf[nt]);
        }
        __syncthreads();
        if (c + 2 < nch) issue(c + 2);
    }

    int n0 = blockIdx.x * NT;
#pragma unroll
    for (int mt = 0; mt < MT; mt++) {
#pragma unroll
        for (int nt = 0; nt < NTT; nt++) {
            int r = wm + mt * 16 + lg;
            int cc = wn + nt * 8 + lr * 2;
            float v0 = acc[mt][nt][0], v1 = acc[mt][nt][1];
            float v2 = acc[mt][nt][2], v3 = acc[mt][nt][3];
            if (EPI == 1) {
                v0 = 1.f / (1.f + __expf(-v0));
                v1 = 1.f / (1.f + __expf(-v1));
                v2 = 1.f / (1.f + __expf(-v2));
                v3 = 1.f / (1.f + __expf(-v3));
            }
            if (EPI == 2) {
                float b0 = bias[n0 + cc], b1 = bias[n0 + cc + 1];
                v0 += b0; v1 += b1; v2 += b0; v3 += b1;
            }
            *(float2*)(Cp + (size_t)r * ldc + cc) = make_float2(v0, v1);
            *(float2*)(Cp + (size_t)(r + 8) * ldc + cc) = make_float2(v2, v3);
        }
    }
}

// ================= fused flash attention (cp.async, double-buffered KV) =====
// CTA: 128 Q rows x one (b,h). 8 warps, 16 rows each. 1/8 scale in softmax.
#define FLASH_SMEM ((128 * 68 + 4 * 64 * 68) * 4)

__global__ void __launch_bounds__(256, 2) flash_kernel() {
    extern __shared__ float fs[];
    float* Qs = fs;                       // 128 x 68 (Q, then per-warp P)
    float* Ks = fs + 128 * 68;            // 2 x 64 x 68
    float* Vs = Ks + 2 * 64 * 68;         // 2 x 64 x 68

    int tid = threadIdx.x;
    int wid = tid >> 5, lane = tid & 31;
    int lg = lane >> 2, lr = lane & 3;
    int bh = blockIdx.y, b = bh >> 3, h = bh & 7;
    int l0 = blockIdx.x * 128;

    const float* Qp = g_q + (size_t)(b * L_ + l0) * DM_ + h * 64;
    const float* Kp = g_k + (size_t)(b * S_) * DM_ + h * 64;
    const float* Vp = g_v + (size_t)(b * S_) * DM_ + h * 64;

    // Q: 128 rows x 64 floats
#pragma unroll
    for (int i = 0; i < 8; i++) {
        int idx = i * 256 + tid, r = idx >> 4, c4 = (idx & 15) * 4;
        cpa16(s2u(Qs + r * 68 + c4), Qp + (size_t)r * DM_ + c4);
    }
    CPA_COMMIT();

    auto issueKV = [&](int sc) {
        float* kd = Ks + (sc & 1) * 64 * 68;
        float* vd = Vs + (sc & 1) * 64 * 68;
        const float* ks = Kp + (size_t)sc * 64 * DM_;
        const float* vs = Vp + (size_t)sc * 64 * DM_;
#pragma unroll
        for (int i = 0; i < 4; i++) {
            int idx = i * 256 + tid, r = idx >> 4, c4 = (idx & 15) * 4;
            cpa16(s2u(kd + r * 68 + c4), ks + (size_t)r * DM_ + c4);
            cpa16(s2u(vd + r * 68 + c4), vs + (size_t)r * DM_ + c4);
        }
        CPA_COMMIT();
    };
    issueKV(0);
    issueKV(1);

    // Q fragments
    CPA_WAIT2();
    __syncthreads();
    uint32_t qf[8][4];
    {
        const uint32_t* Qu = (const uint32_t*)Qs;
        int r = wid * 16 + lg;
#pragma unroll
        for (int kk = 0; kk < 8; kk++) {
            qf[kk][0] = Qu[r * 68 + kk * 8 + lr];
            qf[kk][1] = Qu[(r + 8) * 68 + kk * 8 + lr];
            qf[kk][2] = Qu[r * 68 + kk * 8 + lr + 4];
            qf[kk][3] = Qu[(r + 8) * 68 + kk * 8 + lr + 4];
        }
    }
    __syncthreads();
    uint32_t* Pwu = (uint32_t*)(Qs + wid * 16 * 68);   // warp-private P slice

    float m0 = -1e30f, m1 = -1e30f, l0s = 0.f, l1s = 0.f;
    float o[8][4];
#pragma unroll
    for (int nt = 0; nt < 8; nt++)
#pragma unroll
        for (int q = 0; q < 4; q++) o[nt][q] = 0.f;

    for (int sc = 0; sc < 8; sc++) {
        if (sc < 7) { CPA_WAIT1(); } else { CPA_WAIT0(); }
        __syncthreads();
        const uint32_t* Ku = (const uint32_t*)(Ks + (sc & 1) * 64 * 68);
        const uint32_t* Vu = (const uint32_t*)(Vs + (sc & 1) * 64 * 68);

        // ---- S = Q . K^T  (warp: 16 x 64, raw scores) ----
        float s[8][4];
#pragma unroll
        for (int nt = 0; nt < 8; nt++)
#pragma unroll
            for (int q = 0; q < 4; q++) s[nt][q] = 0.f;
#pragma unroll
        for (int kk = 0; kk < 8; kk++) {
            uint32_t bf[8][2];
#pragma unroll
            for (int nt = 0; nt < 8; nt++) {
                int r = nt * 8 + lg;
                bf[nt][0] = Ku[r * 68 + kk * 8 + lr];
                bf[nt][1] = Ku[r * 68 + kk * 8 + lr + 4];
            }
#pragma unroll
            for (int nt = 0; nt < 8; nt++)
                mma_tf32(s[nt], qf[kk], bf[nt]);
        }

        // ---- online softmax (1/8 scale folded into exponent) ----
        float cm0 = -1e30f, cm1 = -1e30f;
#pragma unroll
        for (int nt = 0; nt < 8; nt++) {
            cm0 = fmaxf(cm0, fmaxf(s[nt][0], s[nt][1]));
            cm1 = fmaxf(cm1, fmaxf(s[nt][2], s[nt][3]));
        }
        cm0 = fmaxf(cm0, __shfl_xor_sync(~0u, cm0, 1));
        cm0 = fmaxf(cm0, __shfl_xor_sync(~0u, cm0, 2));
        cm1 = fmaxf(cm1, __shfl_xor_sync(~0u, cm1, 1));
        cm1 = fmaxf(cm1, __shfl_xor_sync(~0u, cm1, 2));
        float nm0 = fmaxf(m0, cm0), nm1 = fmaxf(m1, cm1);
        float a0 = __expf((m0 - nm0) * 0.125f), a1 = __expf((m1 - nm1) * 0.125f);
        float rs0 = 0.f, rs1 = 0.f;
#pragma unroll
        for (int nt = 0; nt < 8; nt++) {
            float p0 = __expf((s[nt][0] - nm0) * 0.125f);
            float p1 = __expf((s[nt][1] - nm0) * 0.125f);
            float p2 = __expf((s[nt][2] - nm1) * 0.125f);
            float p3 = __expf((s[nt][3] - nm1) * 0.125f);
            rs0 += p0 + p1; rs1 += p2 + p3;
            int cbase = nt * 8 + 2 * lr;
            Pwu[lg * 68 + cbase]           = __float_as_uint(p0);
            Pwu[lg * 68 + cbase + 1]       = __float_as_uint(p1);
            Pwu[(lg + 8) * 68 + cbase]     = __float_as_uint(p2);
            Pwu[(lg + 8) * 68 + cbase + 1] = __float_as_uint(p3);
        }
        rs0 += __shfl_xor_sync(~0u, rs0, 1); rs0 += __shfl_xor_sync(~0u, rs0, 2);
        rs1 += __shfl_xor_sync(~0u, rs1, 1); rs1 += __shfl_xor_sync(~0u, rs1, 2);
        l0s = l0s * a0 + rs0; l1s = l1s * a1 + rs1;
        m0 = nm0; m1 = nm1;
#pragma unroll
        for (int nt = 0; nt < 8; nt++) {
            o[nt][0] *= a0; o[nt][1] *= a0;
            o[nt][2] *= a1; o[nt][3] *= a1;
        }
        __syncwarp();

        // ---- O += P . V  (V read K-major directly) ----
#pragma unroll
        for (int kk = 0; kk < 8; kk++) {
            uint32_t pf[4];
            pf[0] = Pwu[lg * 68 + kk * 8 + lr];
            pf[1] = Pwu[(lg + 8) * 68 + kk * 8 + lr];
            pf[2] = Pwu[lg * 68 + kk * 8 + lr + 4];
            pf[3] = Pwu[(lg + 8) * 68 + kk * 8 + lr + 4];
            uint32_t bf[8][2];
#pragma unroll
            for (int nt = 0; nt < 8; nt++) {
                bf[nt][0] = Vu[(kk * 8 + lr) * 68 + nt * 8 + lg];
                bf[nt][1] = Vu[(kk * 8 + lr + 4) * 68 + nt * 8 + lg];
            }
#pragma unroll
            for (int nt = 0; nt < 8; nt++)
                mma_tf32(o[nt], pf, bf[nt]);
        }
        __syncthreads();
        if (sc + 2 < 8) issueKV(sc + 2);
    }

    // ---- finalize ----
    float inv0 = 1.f / l0s, inv1 = 1.f / l1s;
    int orow = l0 + wid * 16 + lg;
    float* Op = g_att + (size_t)(b * L_ + orow) * DM_ + h * 64;
#pragma unroll
    for (int nt = 0; nt < 8; nt++) {
        int cc = nt * 8 + 2 * lr;
        *(float2*)(Op + cc) = make_float2(o[nt][0] * inv0, o[nt][1] * inv0);
        *(float2*)(Op + 8 * DM_ + cc) = make_float2(o[nt][2] * inv1, o[nt][3] * inv1);
    }
}

// ================= final: gate * fc + residual + LayerNorm ==================
__global__ void final_kernel(const float* __restrict__ xs,
                             const float* __restrict__ lng,
                             const float* __restrict__ lnb,
                             float* __restrict__ out) {
    int row = blockIdx.x;
    int b = row >> 10;
    int l = row & 1023;
    int s = l & (S_ - 1);
    int d1 = threadIdx.x, d2 = threadIdx.x + 256;
    size_t ro = (size_t)row * DM_;
    size_t go = (size_t)(b * S_ + s) * DM_;
    float v1 = xs[ro + d1] + g_gamma[go + d1] * g_fc[ro + d1];
    float v2 = xs[ro + d2] + g_gamma[go + d2] * g_fc[ro + d2];
    float sum = v1 + v2, sq = v1 * v1 + v2 * v2;
#pragma unroll
    for (int o = 16; o; o >>= 1) {
        sum += __shfl_xor_sync(0xffffffffu, sum, o);
        sq  += __shfl_xor_sync(0xffffffffu, sq,  o);
    }
    __shared__ float rs[8], rq[8];
    int w = threadIdx.x >> 5, lane = threadIdx.x & 31;
    if (lane == 0) { rs[w] = sum; rq[w] = sq; }
    __syncthreads();
    float tsum = 0.f, tsq = 0.f;
#pragma unroll
    for (int i = 0; i < 8; i++) { tsum += rs[i]; tsq += rq[i]; }
    float mu = tsum * (1.f / DM_);
    float var = tsq * (1.f / DM_) - mu * mu;
    float inv = rsqrtf(var + 1e-5f);
    out[ro + d1] = (v1 - mu) * inv * lng[d1] + lnb[d1];
    out[ro + d2] = (v2 - mu) * inv * lng[d2] + lnb[d2];
}

// ================= launch =================
extern "C" void kernel_launch(void* const* d_in, const int* in_sizes, int n_in,
                              void* d_out, int out_size) {
    const float* x_spatial  = (const float*)d_in[0];
    const float* x_velocity = (const float*)d_in[1];
    const float* w_gamma    = (const float*)d_in[2];
    const float* w3 = (const float*)d_in[3];  const float* b3 = (const float*)d_in[4];
    const float* w5 = (const float*)d_in[5];  const float* b5 = (const float*)d_in[6];
    const float* w7 = (const float*)d_in[7];  const float* b7 = (const float*)d_in[8];
    const float* rel = (const float*)d_in[9];
    const float* dww = (const float*)d_in[10]; const float* dwb = (const float*)d_in[11];
    const float* wq  = (const float*)d_in[12];
    const float* wk  = (const float*)d_in[13];
    const float* wv  = (const float*)d_in[14];
    const float* fcw = (const float*)d_in[15]; const float* fcb = (const float*)d_in[16];
    const float* lng = (const float*)d_in[17]; const float* lnb = (const float*)d_in[18];
    float* out = (float*)d_out;

    float *p_gamma, *p_q, *p_k, *p_v, *p_att, *p_fc, *p_xpe;
    cudaGetSymbolAddress((void**)&p_gamma, g_gamma);
    cudaGetSymbolAddress((void**)&p_q,     g_q);
    cudaGetSymbolAddress((void**)&p_k,     g_k);
    cudaGetSymbolAddress((void**)&p_v,     g_v);
    cudaGetSymbolAddress((void**)&p_att,   g_att);
    cudaGetSymbolAddress((void**)&p_fc,    g_fc);
    cudaGetSymbolAddress((void**)&p_xpe,   g_xpe);

    cudaFuncSetAttribute(mma_gemm<128, 0>, cudaFuncAttributeMaxDynamicSharedMemorySize, SMG);
    cudaFuncSetAttribute(mma_gemm<128, 1>, cudaFuncAttributeMaxDynamicSharedMemorySize, SMG);
    cudaFuncSetAttribute(mma_gemm<128, 2>, cudaFuncAttributeMaxDynamicSharedMemorySize, SMG);
    cudaFuncSetAttribute(flash_kernel, cudaFuncAttributeMaxDynamicSharedMemorySize, FLASH_SMEM);

    // 1-3: prologue
    mean_rel_kernel<<<S_, D3_>>>(rel);
    conv_kernel<<<dim3(B_, S_ / 32), D3_>>>(x_velocity, w3, b3, w5, b5, w7, b7);
    xpe_kernel<<<B_ * S_, D3_>>>(rel, dww, dwb);

    // 4: gamma = sigmoid(xv @ w_gamma^T)     M=4096 N=512 K=64
    mma_gemm<128, 1><<<dim3(4, 32), 256, SMG>>>(
        x_velocity, w_gamma, nullptr, p_gamma, 64, 64, 64, DM_);
    // 5: q = x_spatial @ wq^T                M=8192 N=512 K=512
    mma_gemm<128, 0><<<dim3(4, 64), 256, SMG>>>(
        x_spatial, wq, nullptr, p_q, SD_, SD_, SD_, DM_);
    // 6/7: k, v = x_pe @ wk^T / wv^T         M=4096 N=512 K=192
    mma_gemm<128, 0><<<dim3(4, 32), 256, SMG>>>(
        p_xpe, wk, nullptr, p_k, D3_, D3_, D3_, DM_);
    mma_gemm<128, 0><<<dim3(4, 32), 256, SMG>>>(
        p_xpe, wv, nullptr, p_v, D3_, D3_, D3_, DM_);
    // 8: fused flash attention -> g_att
    flash_kernel<<<dim3(L_ / 128, BH_), 256, FLASH_SMEM>>>();
    // 9: fc = att @ fc_w^T + fc_b            M=8192 N=512 K=512
    mma_gemm<128, 2><<<dim3(4, 64), 256, SMG>>>(
        p_att, fcw, fcb, p_fc, DM_, DM_, DM_, DM_);
    // 10: gate + residual + layernorm
    final_kernel<<<B_ * L_, 256>>>(x_spatial, lng, lnb, out);
}